// round 1
// baseline (speedup 1.0000x reference)
#include <cuda_runtime.h>
#include <cuda_bf16.h>
#include <cstdint>

#define NB   4
#define TT   2048
#define LL   2048
#define DV   64
#define DQIN 32
#define DF   34

// Scratch (device globals; no allocation allowed)
__device__ float g_V[3 * NB * LL * DV];        // 6 MB: per-modality V rows
__device__ float g_x[3 * NB * LL];             // key scalars
__device__ float g_alpha[3 * NB * TT];
__device__ float g_beta[3 * NB * TT];
__device__ int   g_cut[3 * NB * TT];
__device__ float g_wa[3 * DQIN];
__device__ float g_wb[3 * DQIN];
__device__ float g_ca[3];
__device__ float g_cb[3];
__device__ float g_invtau[3];

// ---------------------------------------------------------------------------
// prep0: collapse K-path weights.  Q.K = alpha + beta * x  with
//   alpha = ref . wa + ca,  beta = ref . wb + cb
// wa[d] = Wq[d][0] - sum_{j=1..63} Wq[d][j]*bk[j-1],  ca = -bk[63]
// wb[d] =          - sum_{j=1..63} Wq[d][j]*Wk[j-1],  cb = -Wk[63]
// ---------------------------------------------------------------------------
__global__ void prep0(const float* __restrict__ Wq,
                      const float* __restrict__ Wk1, const float* __restrict__ bk1, const float* __restrict__ lt1,
                      const float* __restrict__ Wk2, const float* __restrict__ bk2, const float* __restrict__ lt2,
                      const float* __restrict__ Wk3, const float* __restrict__ bk3, const float* __restrict__ lt3)
{
    int tid = threadIdx.x;
    const float* Wk[3] = {Wk1, Wk2, Wk3};
    const float* bk[3] = {bk1, bk2, bk3};
    const float* lt[3] = {lt1, lt2, lt3};
    if (tid < 96) {
        int m = tid >> 5, d = tid & 31;
        float sa = Wq[d * 64 + 0];
        float sb = 0.f;
        #pragma unroll 1
        for (int j = 1; j < 64; j++) {
            float w = Wq[d * 64 + j];
            sa -= w * bk[m][j - 1];
            sb -= w * Wk[m][j - 1];
        }
        g_wa[m * DQIN + d] = sa;
        g_wb[m * DQIN + d] = sb;
        if (d == 0) {
            g_ca[m] = -bk[m][63];
            g_cb[m] = -Wk[m][63];
            g_invtau[m] = __expf(-lt[m][0]);
        }
    }
}

// ---------------------------------------------------------------------------
// prep1: per (m,n,t) alpha/beta + mask cutoff (count of t_l <= ref_t[t])
// ---------------------------------------------------------------------------
__global__ void prep1(const float* __restrict__ ref_data, const float* __restrict__ ref_t,
                      const float* __restrict__ t1, const float* __restrict__ t2,
                      const float* __restrict__ t3)
{
    int idx = blockIdx.x * blockDim.x + threadIdx.x;  // m*NB*TT + n*TT + t
    if (idx >= 3 * NB * TT) return;
    int m = idx / (NB * TT);
    int r = idx - m * (NB * TT);
    int n = r / TT;
    int t = r - n * TT;

    const float* rd = ref_data + (size_t)(n * TT + t) * DQIN;
    float a = g_ca[m], b = g_cb[m];
    #pragma unroll
    for (int d = 0; d < DQIN; d++) {
        float v = rd[d];
        a = fmaf(v, g_wa[m * DQIN + d], a);
        b = fmaf(v, g_wb[m * DQIN + d], b);
    }
    g_alpha[idx] = a;
    g_beta[idx]  = b;

    const float* tl = (m == 0 ? t1 : (m == 1 ? t2 : t3)) + (size_t)n * LL;
    float rt = ref_t[n * TT + t];
    int lo = 0, hi = LL;
    while (lo < hi) {
        int mid = (lo + hi) >> 1;
        if (tl[mid] <= rt) lo = mid + 1; else hi = mid;
    }
    g_cut[idx] = lo;
}

// ---------------------------------------------------------------------------
// prep2: V = data[:, :32] @ Wv + bv ; gather x = data[:, 33]
// one thread per V element
// ---------------------------------------------------------------------------
__global__ void prep2(const float* __restrict__ d1, const float* __restrict__ d2, const float* __restrict__ d3,
                      const float* __restrict__ Wv1, const float* __restrict__ bv1,
                      const float* __restrict__ Wv2, const float* __restrict__ bv2,
                      const float* __restrict__ Wv3, const float* __restrict__ bv3)
{
    int idx = blockIdx.x * blockDim.x + threadIdx.x;
    if (idx >= 3 * NB * LL * DV) return;
    int j   = idx & (DV - 1);
    int row = idx >> 6;                 // m*NB*LL + n*LL + l
    int m   = row / (NB * LL);
    int r   = row - m * (NB * LL);

    const float* data = (m == 0 ? d1 : (m == 1 ? d2 : d3)) + (size_t)r * DF;
    const float* Wv   = (m == 0 ? Wv1 : (m == 1 ? Wv2 : Wv3));
    const float* bv   = (m == 0 ? bv1 : (m == 1 ? bv2 : bv3));

    float s = bv[j];
    #pragma unroll
    for (int i = 0; i < DQIN; i++)
        s = fmaf(data[i], Wv[i * 64 + j], s);
    g_V[idx] = s;
    if (j == 0) g_x[row] = data[33];
}

// ---------------------------------------------------------------------------
// attn: 64 queries per block, 2 half-threads per query (32 V dims each).
// Key tiles of 128 staged in smem. All fp32.
// softmax(S*mask)*mask with S<=0:
//   if cut < L: row max is exactly 0, denom gets +(L-cut)*exp(-M), M=0
//   if cut == L: need true max pass over the row
// ---------------------------------------------------------------------------
#define TQ 64
#define KT 128

__global__ __launch_bounds__(128, 6)
void attn(float* __restrict__ out)
{
    __shared__ float  xs[KT];
    __shared__ float4 Vs[KT * 16];   // [k][16 float4] = 32 KB
    __shared__ int    swm[4];

    const int m    = blockIdx.z;
    const int n    = blockIdx.y;
    const int tile = blockIdx.x;
    const int tid  = threadIdx.x;
    const int q    = tid & 63;       // query within tile
    const int half = tid >> 6;       // 0: dims 0..31, 1: dims 32..63
    const int t    = tile * TQ + q;
    const int ridx = (m * NB + n) * TT + t;

    const float a      = g_alpha[ridx];
    const float b      = g_beta[ridx];
    const float invtau = g_invtau[m];
    const int   cut    = g_cut[ridx];

    // block max cutoff (robust reduction)
    int wmax = __reduce_max_sync(0xffffffffu, cut);
    if ((tid & 31) == 0) swm[tid >> 5] = wmax;
    __syncthreads();
    const int maxcut = max(max(swm[0], swm[1]), max(swm[2], swm[3]));

    const float* __restrict__ xg = g_x + (size_t)(m * NB + n) * LL;
    const float* __restrict__ Vg = g_V + (size_t)(m * NB + n) * LL * DV;

    // M: row max of scores (only needed if no masked entries exist)
    float M = 0.f;
    if (cut == LL) {
        float mx = -3.4e38f;
        #pragma unroll 4
        for (int l = 0; l < LL; l++) {
            float z = fmaf(b, __ldg(xg + l), a);
            mx = fmaxf(mx, -z * z * invtau);
        }
        M = mx;
    }
    const float negM = -M;

    float4 acc[8];
    #pragma unroll
    for (int i = 0; i < 8; i++) acc[i] = make_float4(0.f, 0.f, 0.f, 0.f);
    float den = 0.f;

    for (int base = 0; base < maxcut; base += KT) {
        if (tid < KT) xs[tid] = xg[base + tid];
        const float4* Vg4 = (const float4*)(Vg + (size_t)base * DV);
        #pragma unroll
        for (int i = 0; i < 16; i++)
            Vs[tid + i * 128] = Vg4[tid + i * 128];
        __syncthreads();

        const int klim = min(KT, cut - base);   // keys valid for THIS thread
        for (int k = 0; k < klim; k++) {
            float z  = fmaf(b, xs[k], a);
            float w  = __expf(fmaf(-(z * z), invtau, negM));
            den += w;
            const float4* vrow = &Vs[k * 16 + half * 8];
            #pragma unroll
            for (int i = 0; i < 8; i++) {
                float4 v = vrow[i];
                acc[i].x = fmaf(w, v.x, acc[i].x);
                acc[i].y = fmaf(w, v.y, acc[i].y);
                acc[i].z = fmaf(w, v.z, acc[i].z);
                acc[i].w = fmaf(w, v.w, acc[i].w);
            }
        }
        __syncthreads();
    }

    // masked entries contribute exp(0 - M) each to the softmax denominator
    const float denom = den + (float)(LL - cut) * __expf(negM);
    const float inv   = 1.f / denom;

    float4* op = (float4*)(out + (size_t)ridx * DV + half * 32);
    #pragma unroll
    for (int i = 0; i < 8; i++)
        op[i] = make_float4(acc[i].x * inv, acc[i].y * inv, acc[i].z * inv, acc[i].w * inv);
}

// ---------------------------------------------------------------------------
extern "C" void kernel_launch(void* const* d_in, const int* in_sizes, int n_in,
                              void* d_out, int out_size)
{
    const float* ref_data = (const float*)d_in[0];
    const float* ref_t    = (const float*)d_in[1];
    const float* m1_data  = (const float*)d_in[2];
    const float* m1_t     = (const float*)d_in[3];
    const float* m2_data  = (const float*)d_in[4];
    const float* m2_t     = (const float*)d_in[5];
    const float* m3_data  = (const float*)d_in[6];
    const float* m3_t     = (const float*)d_in[7];
    const float* Wq       = (const float*)d_in[8];
    const float* Wk1      = (const float*)d_in[9];
    const float* bk1      = (const float*)d_in[10];
    const float* Wv1      = (const float*)d_in[11];
    const float* bv1      = (const float*)d_in[12];
    const float* lt1      = (const float*)d_in[13];
    const float* Wk2      = (const float*)d_in[14];
    const float* bk2      = (const float*)d_in[15];
    const float* Wv2      = (const float*)d_in[16];
    const float* bv2      = (const float*)d_in[17];
    const float* lt2      = (const float*)d_in[18];
    const float* Wk3      = (const float*)d_in[19];
    const float* bk3      = (const float*)d_in[20];
    const float* Wv3      = (const float*)d_in[21];
    const float* bv3      = (const float*)d_in[22];
    const float* lt3      = (const float*)d_in[23];

    prep0<<<1, 128>>>(Wq, Wk1, bk1, lt1, Wk2, bk2, lt2, Wk3, bk3, lt3);
    prep1<<<(3 * NB * TT + 127) / 128, 128>>>(ref_data, ref_t, m1_t, m2_t, m3_t);
    prep2<<<(3 * NB * LL * DV) / 256, 256>>>(m1_data, m2_data, m3_data,
                                             Wv1, bv1, Wv2, bv2, Wv3, bv3);
    attn<<<dim3(TT / TQ, NB, 3), 128>>>((float*)d_out);
}